// round 15
// baseline (speedup 1.0000x reference)
#include <cuda_runtime.h>
#include <cuda_bf16.h>
#include <cstdint>

#define N_P 100000
#define N_A 50000
#define E_C 1600000
#define E_W 800000
#define IND 768
#define H   128
#define HH  (128*128)

// ---------------- scratch (device globals; no allocation) ----------------
__device__ float g_hp[(size_t)N_P * H];
__device__ float g_ha[(size_t)N_A * H];
__device__ float g_zp[(size_t)N_P * H];
__device__ float g_za[(size_t)N_A * H];
__device__ float g_aggc[(size_t)N_P * H];
__device__ float g_aggw[(size_t)N_P * H];
__device__ float g_aggr[(size_t)N_A * H];
__device__ float g_bp[2 * H];
__device__ __align__(16) __nv_bfloat16 g_wPh[128 * IND], g_wPl[128 * IND];
__device__ __align__(16) __nv_bfloat16 g_wAh[128 * IND], g_wAl[128 * IND];
__device__ __align__(16) __nv_bfloat16 g_wLPh[2][128 * 384], g_wLPl[2][128 * 384];
__device__ __align__(16) __nv_bfloat16 g_wLAh[2][128 * 256], g_wLAl[2][128 * 256];
__device__ int g_cptr[N_P + 1], g_cidx[E_C];
__device__ int g_wptr[N_P + 1], g_widx[E_W];
__device__ int g_rptr[N_A + 1], g_ridx[E_W];
__device__ int g_tmpA[N_P + 1];
__device__ int g_bsA[136];

// ---------------- helpers ----------------
__device__ __forceinline__ uint32_t s2u(const void* p) {
    uint32_t a;
    asm("{ .reg .u64 t; cvta.to.shared.u64 t, %1; cvt.u32.u64 %0, t; }" : "=r"(a) : "l"(p));
    return a;
}

__device__ __forceinline__ void ldsm4(uint32_t addr, uint32_t* r) {
    asm volatile("ldmatrix.sync.aligned.m8n8.x4.shared.b16 {%0,%1,%2,%3}, [%4];"
                 : "=r"(r[0]), "=r"(r[1]), "=r"(r[2]), "=r"(r[3]) : "r"(addr));
}

__device__ __forceinline__ void mma16816(float* c, const uint32_t* a, uint32_t b0, uint32_t b1) {
    asm volatile("mma.sync.aligned.m16n8k16.row.col.f32.bf16.bf16.f32 "
                 "{%0,%1,%2,%3}, {%4,%5,%6,%7}, {%8,%9}, {%0,%1,%2,%3};"
                 : "+f"(c[0]), "+f"(c[1]), "+f"(c[2]), "+f"(c[3])
                 : "r"(a[0]), "r"(a[1]), "r"(a[2]), "r"(a[3]), "r"(b0), "r"(b1));
}

__device__ __forceinline__ void cpa16(uint32_t dst, const void* src, int sz) {
    asm volatile("cp.async.cg.shared.global [%0], [%1], 16, %2;"
                 :: "r"(dst), "l"(src), "r"(sz));
}
#define CP_COMMIT() asm volatile("cp.async.commit_group;" ::: "memory")

__device__ __forceinline__ uint32_t prmt7632(uint32_t a, uint32_t b) {
    uint32_t d; asm("prmt.b32 %0, %1, %2, 0x7632;" : "=r"(d) : "r"(a), "r"(b)); return d;
}
__device__ __forceinline__ float lopart(uint32_t xb) {
    float x = __uint_as_float(xb);
    return x - __uint_as_float(xb & 0xffff0000u);
}
__device__ __forceinline__ uint32_t bf16x2pack(float hi, float lo) {
    uint32_t d; asm("cvt.rn.bf16x2.f32 %0, %1, %2;" : "=r"(d) : "f"(hi), "f"(lo)); return d;
}

__device__ __forceinline__ void split_bf16(float v, __nv_bfloat16& h, __nv_bfloat16& l) {
    h = __float2bfloat16(v);
    l = __float2bfloat16(v - __bfloat162float(h));
}

__host__ __device__ __forceinline__ int permk(int k) {
    return (k & ~15) | (k & 8) | ((k & 3) << 1) | ((k >> 2) & 1);
}

// ---------------- weight prep ----------------
__global__ void prep_projw(const float* __restrict__ W, __nv_bfloat16* __restrict__ hi,
                           __nv_bfloat16* __restrict__ lo) {
    int i = blockIdx.x * 256 + threadIdx.x;
    if (i >= IND * 128) return;
    int k = i >> 7, n = i & 127;
    __nv_bfloat16 h, l;
    split_bf16(W[i], h, l);
    int kk = permk(k);
    hi[n * IND + kk] = h;
    lo[n * IND + kk] = l;
}

__global__ void prep_layerw(const float* __restrict__ Wl, const float* __restrict__ bl,
                            const float* __restrict__ Wr) {
    int l = blockIdx.y;
    int i = blockIdx.x * 256 + threadIdx.x;
    if (i >= HH) return;
    int k = i >> 7, n = i & 127;
    int kk = permk(k);
    __nv_bfloat16 h, lo;
    split_bf16(0.5f * Wl[(l * 3 + 0) * HH + i], h, lo);
    g_wLPh[l][n * 384 + kk] = h;       g_wLPl[l][n * 384 + kk] = lo;
    split_bf16(0.5f * Wl[(l * 3 + 1) * HH + i], h, lo);
    g_wLPh[l][n * 384 + 128 + kk] = h; g_wLPl[l][n * 384 + 128 + kk] = lo;
    split_bf16(0.5f * (Wr[(l * 3 + 0) * HH + i] + Wr[(l * 3 + 1) * HH + i]), h, lo);
    g_wLPh[l][n * 384 + 256 + kk] = h; g_wLPl[l][n * 384 + 256 + kk] = lo;
    split_bf16(Wl[(l * 3 + 2) * HH + i], h, lo);
    g_wLAh[l][n * 256 + kk] = h;       g_wLAl[l][n * 256 + kk] = lo;
    split_bf16(Wr[(l * 3 + 2) * HH + i], h, lo);
    g_wLAh[l][n * 256 + 128 + kk] = h; g_wLAl[l][n * 256 + 128 + kk] = lo;
    if (blockIdx.x == 0 && i < H)
        g_bp[l * H + i] = 0.5f * (bl[(l * 3 + 0) * H + i] + bl[(l * 3 + 1) * H + i]);
}

// ---------------- CSR build (hierarchical scan) ----------------
__global__ void zero_int(int* __restrict__ p, int n) {
    int i = blockIdx.x * blockDim.x + threadIdx.x;
    if (i < n) p[i] = 0;
}
__global__ void count_k(const int* __restrict__ dst, int* __restrict__ cnt, int n) {
    int i = blockIdx.x * blockDim.x + threadIdx.x;
    if (i < n) atomicAdd(&cnt[dst[i]], 1);
}
__global__ void scan_blk(const int* __restrict__ cnt, int* __restrict__ ptr,
                         int* __restrict__ bsum, int n) {
    __shared__ int ss[1024];
    int tid = threadIdx.x;
    int i = blockIdx.x * 1024 + tid;
    int v = (i < n) ? cnt[i] : 0;
    ss[tid] = v;
    __syncthreads();
    #pragma unroll
    for (int off = 1; off < 1024; off <<= 1) {
        int t = (tid >= off) ? ss[tid - off] : 0;
        __syncthreads();
        ss[tid] += t;
        __syncthreads();
    }
    if (i < n) ptr[i] = ss[tid] - v;
    if (tid == 1023) bsum[blockIdx.x] = ss[1023];
}
__global__ void scan_top(int* __restrict__ bsum, int nb) {
    __shared__ int ss[128];
    int tid = threadIdx.x;
    int v = (tid < nb) ? bsum[tid] : 0;
    ss[tid] = v;
    __syncthreads();
    #pragma unroll
    for (int off = 1; off < 128; off <<= 1) {
        int t = (tid >= off) ? ss[tid - off] : 0;
        __syncthreads();
        ss[tid] += t;
        __syncthreads();
    }
    if (tid < nb) bsum[tid] = ss[tid] - v;
    if (tid == 127) bsum[nb] = ss[127];
}
__global__ void add_off(int* __restrict__ ptr, const int* __restrict__ bsum, int n, int nb) {
    int i = blockIdx.x * blockDim.x + threadIdx.x;
    if (i < n) ptr[i] += bsum[i >> 10];
    else if (i == n) ptr[n] = bsum[nb];
}
__global__ void fill_k(const int* __restrict__ src, const int* __restrict__ dst,
                       const int* __restrict__ ptr, int* __restrict__ tmp,
                       int* __restrict__ cidx, int n) {
    int i = blockIdx.x * blockDim.x + threadIdx.x;
    if (i < n) {
        int d = dst[i];
        int p = atomicAdd(&tmp[d], 1);
        cidx[ptr[d] + p] = src[i];
    }
}

// ---------------- mean aggregation: one warp per destination node ----------------
__global__ void agg_mean(const float* __restrict__ feat, const int* __restrict__ ptr,
                         const int* __restrict__ idx, float* __restrict__ out, int n) {
    int w = (blockIdx.x * blockDim.x + threadIdx.x) >> 5;
    int lane = threadIdx.x & 31;
    if (w >= n) return;
    int beg = ptr[w], end = ptr[w + 1];
    float ax = 0.f, ay = 0.f, az = 0.f, aw = 0.f;
    int e = beg;
    for (; e + 8 <= end; e += 8) {
        #pragma unroll
        for (int j = 0; j < 8; j += 4) {
            int s0 = idx[e + j], s1 = idx[e + j + 1], s2 = idx[e + j + 2], s3 = idx[e + j + 3];
            float4 v0 = ((const float4*)(feat + (size_t)s0 * H))[lane];
            float4 v1 = ((const float4*)(feat + (size_t)s1 * H))[lane];
            float4 v2 = ((const float4*)(feat + (size_t)s2 * H))[lane];
            float4 v3 = ((const float4*)(feat + (size_t)s3 * H))[lane];
            ax += (v0.x + v1.x) + (v2.x + v3.x);
            ay += (v0.y + v1.y) + (v2.y + v3.y);
            az += (v0.z + v1.z) + (v2.z + v3.z);
            aw += (v0.w + v1.w) + (v2.w + v3.w);
        }
    }
    for (; e < end; e++) {
        int s0 = idx[e];
        float4 v0 = ((const float4*)(feat + (size_t)s0 * H))[lane];
        ax += v0.x; ay += v0.y; az += v0.z; aw += v0.w;
    }
    int c = end - beg;
    float inv = 1.0f / (float)(c > 1 ? c : 1);
    float4 r;
    r.x = ax * inv; r.y = ay * inv; r.z = az * inv; r.w = aw * inv;
    ((float4*)(out + (size_t)w * H))[lane] = r;
}

// ---------------- async pipelined warp-MMA GEMM (phase-ordered MMAs) ----------------
#define SMEM_SZ 65536
template <int NMAT, int KC, int EPI>
__global__ __launch_bounds__(256, 2) void pgemm(
    const float* __restrict__ A0, const float* __restrict__ A1, const float* __restrict__ A2,
    const __nv_bfloat16* __restrict__ Bhi, const __nv_bfloat16* __restrict__ Blo,
    const float* __restrict__ bias, const float* __restrict__ lng, const float* __restrict__ lnb,
    const float* __restrict__ res, float* __restrict__ out, int M) {
    extern __shared__ char sm[];
    uint32_t sbase = s2u(sm);
    int t = threadIdx.x, lane = t & 31, wid = t >> 5;
    int wm = wid & 3, wn = wid >> 2;
    int row0 = blockIdx.x * 128;
    const int SEG = KC / NMAT;
    const int NI = KC / 32;
    const float* Aall[3] = {A0, A1, A2};

    int q = lane >> 3, e = lane & 7;

    float acc[2][8][4];
    #pragma unroll
    for (int a = 0; a < 2; a++)
        #pragma unroll
        for (int b = 0; b < 8; b++)
            #pragma unroll
            for (int c = 0; c < 4; c++) acc[a][b][c] = 0.f;

    auto stage = [&](int i) {
        int b = i & 1;
        int k0 = i * 32;
        int mseg = k0 / SEG, kl = k0 - mseg * SEG;
        const float* A = Aall[mseg];
        #pragma unroll
        for (int it = 0; it < 4; it++) {
            int uid = t + 256 * it;
            int r = uid >> 3, u = uid & 7;
            int gr = row0 + r;
            int ok = (gr < M);
            const float* src = A + (size_t)(ok ? gr : 0) * SEG + kl + 4 * u;
            uint32_t dst = sbase + b * 16384 + (uint32_t)(r * 128 + ((u ^ (r & 7)) << 4));
            cpa16(dst, src, ok ? 16 : 0);
        }
        #pragma unroll
        for (int it = 0; it < 2; it++) {
            int uid = t + 256 * it;
            int n = uid >> 2, v = uid & 3;
            size_t go = (size_t)n * KC + k0 + 8 * v;
            uint32_t off = (uint32_t)(n * 64 + ((v ^ ((n >> 1) & 3)) << 4));
            cpa16(sbase + 32768 + b * 8192 + off, Bhi + go, 16);
            cpa16(sbase + 49152 + b * 8192 + off, Blo + go, 16);
        }
        CP_COMMIT();
    };

    stage(0);
    for (int i = 0; i < NI; i++) {
        if (i + 1 < NI) {
            stage(i + 1);
            asm volatile("cp.async.wait_group 1;" ::: "memory");
        } else {
            asm volatile("cp.async.wait_group 0;" ::: "memory");
        }
        __syncthreads();
        int b = i & 1;
        uint32_t aB = sbase + b * 16384;
        uint32_t bhB = sbase + 32768 + b * 8192;
        uint32_t blB = sbase + 49152 + b * 8192;
        #pragma unroll
        for (int ks = 0; ks < 2; ks++) {
            uint32_t AH[2][4], AL[2][4];
            #pragma unroll
            for (int mt = 0; mt < 2; mt++) {
                int arow = wm * 32 + mt * 16 + (q & 1) * 8 + e;
                uint32_t ro = (uint32_t)(arow * 128);
                int u1 = 4 * ks + (q >> 1);
                int u2 = u1 + 2;
                uint32_t x[8];
                ldsm4(aB + ro + (uint32_t)((u1 ^ (arow & 7)) << 4), x);
                ldsm4(aB + ro + (uint32_t)((u2 ^ (arow & 7)) << 4), x + 4);
                AH[mt][0] = prmt7632(x[0], x[2]);
                AH[mt][1] = prmt7632(x[1], x[3]);
                AH[mt][2] = prmt7632(x[4], x[6]);
                AH[mt][3] = prmt7632(x[5], x[7]);
                AL[mt][0] = bf16x2pack(lopart(x[2]), lopart(x[0]));
                AL[mt][1] = bf16x2pack(lopart(x[3]), lopart(x[1]));
                AL[mt][2] = bf16x2pack(lopart(x[6]), lopart(x[4]));
                AL[mt][3] = bf16x2pack(lopart(x[7]), lopart(x[5]));
            }
            // process nt2 in pairs; 3 phases of 8 independent MMAs each
            #pragma unroll
            for (int np = 0; np < 2; np++) {
                uint32_t bh[2][4], bl[2][4];
                #pragma unroll
                for (int j = 0; j < 2; j++) {
                    int nt2 = np * 2 + j;
                    int brow = wn * 64 + nt2 * 16 + (q & 1) * 8 + e;
                    int v = 2 * ks + (q >> 1);
                    uint32_t bo = (uint32_t)(brow * 64 + ((v ^ ((brow >> 1) & 3)) << 4));
                    ldsm4(bhB + bo, bh[j]);
                    ldsm4(blB + bo, bl[j]);
                }
                // phase 1: AH * Bh (8 independent)
                #pragma unroll
                for (int j = 0; j < 2; j++)
                    #pragma unroll
                    for (int mt = 0; mt < 2; mt++)
                        #pragma unroll
                        for (int s = 0; s < 2; s++)
                            mma16816(acc[mt][2 * (np * 2 + j) + s], AH[mt], bh[j][s], bh[j][2 + s]);
                // phase 2: AH * Bl (8 independent)
                #pragma unroll
                for (int j = 0; j < 2; j++)
                    #pragma unroll
                    for (int mt = 0; mt < 2; mt++)
                        #pragma unroll
                        for (int s = 0; s < 2; s++)
                            mma16816(acc[mt][2 * (np * 2 + j) + s], AH[mt], bl[j][s], bl[j][2 + s]);
                // phase 3: AL * Bh (8 independent)
                #pragma unroll
                for (int j = 0; j < 2; j++)
                    #pragma unroll
                    for (int mt = 0; mt < 2; mt++)
                        #pragma unroll
                        for (int s = 0; s < 2; s++)
                            mma16816(acc[mt][2 * (np * 2 + j) + s], AL[mt], bh[j][s], bh[j][2 + s]);
            }
        }
        __syncthreads();
    }

    // ---- epilogue ----
    int la = lane >> 2, lc = 2 * (lane & 3);
    float2 b2[8];
    #pragma unroll
    for (int nt = 0; nt < 8; nt++)
        b2[nt] = *(const float2*)(bias + wn * 64 + nt * 8 + lc);
    #pragma unroll
    for (int mt = 0; mt < 2; mt++)
        #pragma unroll
        for (int nt = 0; nt < 8; nt++) {
            acc[mt][nt][0] += b2[nt].x; acc[mt][nt][1] += b2[nt].y;
            acc[mt][nt][2] += b2[nt].x; acc[mt][nt][3] += b2[nt].y;
        }

    if (EPI == 0) {
        float* red = (float*)sm;
        float s1[2][2], s2[2][2];
        #pragma unroll
        for (int mt = 0; mt < 2; mt++)
            #pragma unroll
            for (int h = 0; h < 2; h++) {
                float a1 = 0.f, a2 = 0.f;
                #pragma unroll
                for (int nt = 0; nt < 8; nt++) {
                    float vx = acc[mt][nt][2 * h], vy = acc[mt][nt][2 * h + 1];
                    a1 += vx + vy;
                    a2 += vx * vx + vy * vy;
                }
                a1 += __shfl_xor_sync(0xffffffffu, a1, 1);
                a1 += __shfl_xor_sync(0xffffffffu, a1, 2);
                a2 += __shfl_xor_sync(0xffffffffu, a2, 1);
                a2 += __shfl_xor_sync(0xffffffffu, a2, 2);
                s1[mt][h] = a1; s2[mt][h] = a2;
            }
        if ((lane & 3) == 0) {
            #pragma unroll
            for (int mt = 0; mt < 2; mt++)
                #pragma unroll
                for (int h = 0; h < 2; h++) {
                    int rl = wm * 32 + mt * 16 + la + h * 8;
                    red[(wn * 128 + rl) * 2 + 0] = s1[mt][h];
                    red[(wn * 128 + rl) * 2 + 1] = s2[mt][h];
                }
        }
        __syncthreads();
        float2 lg2[8], lb2[8];
        #pragma unroll
        for (int nt = 0; nt < 8; nt++) {
            lg2[nt] = *(const float2*)(lng + wn * 64 + nt * 8 + lc);
            lb2[nt] = *(const float2*)(lnb + wn * 64 + nt * 8 + lc);
        }
        #pragma unroll
        for (int mt = 0; mt < 2; mt++)
            #pragma unroll
            for (int h = 0; h < 2; h++) {
                int rl = wm * 32 + mt * 16 + la + h * 8;
                float o1 = red[((1 - wn) * 128 + rl) * 2 + 0];
                float o2 = red[((1 - wn) * 128 + rl) * 2 + 1];
                float mu = (s1[mt][h] + o1) * (1.0f / 128.0f);
                float ex2 = (s2[mt][h] + o2) * (1.0f / 128.0f);
                float rstd = rsqrtf(fmaxf(ex2 - mu * mu, 0.f) + 1e-5f);
                #pragma unroll
                for (int nt = 0; nt < 8; nt++) {
                    float vx = acc[mt][nt][2 * h], vy = acc[mt][nt][2 * h + 1];
                    vx = fmaxf((vx - mu) * rstd * lg2[nt].x + lb2[nt].x, 0.f);
                    vy = fmaxf((vy - mu) * rstd * lg2[nt].y + lb2[nt].y, 0.f);
                    acc[mt][nt][2 * h] = vx; acc[mt][nt][2 * h + 1] = vy;
                }
            }
    } else {
        #pragma unroll
        for (int mt = 0; mt < 2; mt++)
            #pragma unroll
            for (int nt = 0; nt < 8; nt++)
                #pragma unroll
                for (int c = 0; c < 4; c++)
                    acc[mt][nt][c] = fmaxf(acc[mt][nt][c], 0.f);
    }

    #pragma unroll
    for (int mt = 0; mt < 2; mt++)
        #pragma unroll
        for (int h = 0; h < 2; h++) {
            int row = row0 + wm * 32 + mt * 16 + la + h * 8;
            if (row < M) {
                #pragma unroll
                for (int nt = 0; nt < 8; nt++) {
                    int col = wn * 64 + nt * 8 + lc;
                    float vx = acc[mt][nt][2 * h], vy = acc[mt][nt][2 * h + 1];
                    if (EPI == 2) {
                        float2 rv = *(const float2*)(res + (size_t)row * H + col);
                        vx += rv.x; vy += rv.y;
                    }
                    float2 o; o.x = vx; o.y = vy;
                    *(float2*)(out + (size_t)row * H + col) = o;
                }
            }
        }
}

// ---------------- launch: forked-stream graph (2 extra streams, proven footprint) ----------------
extern "C" void kernel_launch(void* const* d_in, const int* in_sizes, int n_in,
                              void* d_out, int out_size) {
    const float* x_paper   = (const float*)d_in[0];
    const float* x_author  = (const float*)d_in[1];
    const float* pw_paper  = (const float*)d_in[2];
    const float* pb_paper  = (const float*)d_in[3];
    const float* lng_paper = (const float*)d_in[4];
    const float* lnb_paper = (const float*)d_in[5];
    const float* pw_author  = (const float*)d_in[6];
    const float* pb_author  = (const float*)d_in[7];
    const float* lng_author = (const float*)d_in[8];
    const float* lnb_author = (const float*)d_in[9];
    const float* Wl = (const float*)d_in[10];
    const float* bl = (const float*)d_in[11];
    const float* Wr = (const float*)d_in[12];
    const int* cs = (const int*)d_in[13];
    const int* cd = (const int*)d_in[14];
    const int* ws = (const int*)d_in[15];
    const int* wd = (const int*)d_in[16];
    const int* rs = (const int*)d_in[17];
    const int* rd = (const int*)d_in[18];
    float* out = (float*)d_out;

    float *hp, *ha, *zp, *za, *aggc, *aggw, *aggr, *bp;
    __nv_bfloat16 *wPh, *wPl, *wAh, *wAl, *wLPh, *wLPl, *wLAh, *wLAl;
    int *cptr, *cidx, *wptr, *widx, *rptr, *ridx, *tmpA, *bsA;
    cudaGetSymbolAddress((void**)&hp, g_hp);
    cudaGetSymbolAddress((void**)&ha, g_ha);
    cudaGetSymbolAddress((void**)&zp, g_zp);
    cudaGetSymbolAddress((void**)&za, g_za);
    cudaGetSymbolAddress((void**)&aggc, g_aggc);
    cudaGetSymbolAddress((void**)&aggw, g_aggw);
    cudaGetSymbolAddress((void**)&aggr, g_aggr);
    cudaGetSymbolAddress((void**)&bp, g_bp);
    cudaGetSymbolAddress((void**)&wPh, g_wPh);
    cudaGetSymbolAddress((void**)&wPl, g_wPl);
    cudaGetSymbolAddress((void**)&wAh, g_wAh);
    cudaGetSymbolAddress((void**)&wAl, g_wAl);
    cudaGetSymbolAddress((void**)&wLPh, g_wLPh);
    cudaGetSymbolAddress((void**)&wLPl, g_wLPl);
    cudaGetSymbolAddress((void**)&wLAh, g_wLAh);
    cudaGetSymbolAddress((void**)&wLAl, g_wLAl);
    cudaGetSymbolAddress((void**)&cptr, g_cptr);
    cudaGetSymbolAddress((void**)&cidx, g_cidx);
    cudaGetSymbolAddress((void**)&wptr, g_wptr);
    cudaGetSymbolAddress((void**)&widx, g_widx);
    cudaGetSymbolAddress((void**)&rptr, g_rptr);
    cudaGetSymbolAddress((void**)&ridx, g_ridx);
    cudaGetSymbolAddress((void**)&tmpA, g_tmpA);
    cudaGetSymbolAddress((void**)&bsA, g_bsA);

    cudaFuncSetAttribute(pgemm<1, IND, 0>, cudaFuncAttributeMaxDynamicSharedMemorySize, SMEM_SZ);
    cudaFuncSetAttribute(pgemm<3, 384, 1>, cudaFuncAttributeMaxDynamicSharedMemorySize, SMEM_SZ);
    cudaFuncSetAttribute(pgemm<2, 256, 1>, cudaFuncAttributeMaxDynamicSharedMemorySize, SMEM_SZ);
    cudaFuncSetAttribute(pgemm<3, 384, 2>, cudaFuncAttributeMaxDynamicSharedMemorySize, SMEM_SZ);
    cudaFuncSetAttribute(pgemm<2, 256, 2>, cudaFuncAttributeMaxDynamicSharedMemorySize, SMEM_SZ);

    static cudaStream_t s1 = nullptr, s2 = nullptr;
    static cudaEvent_t eFork = nullptr, eHP = nullptr, eHA = nullptr,
                       eCc = nullptr, eCr = nullptr, eW1 = nullptr, eW2 = nullptr,
                       eP1 = nullptr, eZA = nullptr, eA2 = nullptr;
    if (!s1) {
        cudaStreamCreateWithFlags(&s1, cudaStreamNonBlocking);
        cudaStreamCreateWithFlags(&s2, cudaStreamNonBlocking);
        cudaEventCreateWithFlags(&eFork, cudaEventDisableTiming);
        cudaEventCreateWithFlags(&eHP, cudaEventDisableTiming);
        cudaEventCreateWithFlags(&eHA, cudaEventDisableTiming);
        cudaEventCreateWithFlags(&eCc, cudaEventDisableTiming);
        cudaEventCreateWithFlags(&eCr, cudaEventDisableTiming);
        cudaEventCreateWithFlags(&eW1, cudaEventDisableTiming);
        cudaEventCreateWithFlags(&eW2, cudaEventDisableTiming);
        cudaEventCreateWithFlags(&eP1, cudaEventDisableTiming);
        cudaEventCreateWithFlags(&eZA, cudaEventDisableTiming);
        cudaEventCreateWithFlags(&eA2, cudaEventDisableTiming);
    }
    cudaStream_t s0 = 0;

    // ---- fork ----
    cudaEventRecord(eFork, s0);
    cudaStreamWaitEvent(s1, eFork, 0);
    cudaStreamWaitEvent(s2, eFork, 0);

    auto build = [&](cudaStream_t st, const int* s, const int* d, int nn, int ne,
                     int* ptr, int* ci) {
        int nb = (nn + 1023) >> 10;
        zero_int<<<(nn + 255) / 256, 256, 0, st>>>(tmpA, nn);
        count_k<<<(ne + 255) / 256, 256, 0, st>>>(d, tmpA, ne);
        scan_blk<<<nb, 1024, 0, st>>>(tmpA, ptr, bsA, nn);
        scan_top<<<1, 128, 0, st>>>(bsA, nb);
        add_off<<<(nn + 256) / 256, 256, 0, st>>>(ptr, bsA, nn, nb);
        zero_int<<<(nn + 255) / 256, 256, 0, st>>>(tmpA, nn);
        fill_k<<<(ne + 255) / 256, 256, 0, st>>>(s, d, ptr, tmpA, ci, ne);
    };

    // ---- s2: layer weights + all CSR builds (hidden under projections) ----
    {
        dim3 g((HH + 255) / 256, 2);
        prep_layerw<<<g, 256, 0, s2>>>(Wl, bl, Wr);
    }
    build(s2, cs, cd, N_P, E_C, cptr, cidx);
    cudaEventRecord(eCc, s2);
    build(s2, rs, rd, N_A, E_W, rptr, ridx);
    cudaEventRecord(eCr, s2);
    build(s2, ws, wd, N_P, E_W, wptr, widx);

    // ---- s0: paper projection ----
    prep_projw<<<(IND * 128 + 255) / 256, 256, 0, s0>>>(pw_paper, wPh, wPl);
    pgemm<1, IND, 0><<<(N_P + 127) / 128, 256, SMEM_SZ, s0>>>(
        x_paper, nullptr, nullptr, wPh, wPl,
        pb_paper, lng_paper, lnb_paper, nullptr, hp, N_P);
    cudaEventRecord(eHP, s0);

    // ---- s1: author projection ----
    prep_projw<<<(IND * 128 + 255) / 256, 256, 0, s1>>>(pw_author, wAh, wAl);
    pgemm<1, IND, 0><<<(N_A + 127) / 128, 256, SMEM_SZ, s1>>>(
        x_author, nullptr, nullptr, wAh, wAl,
        pb_author, lng_author, lnb_author, nullptr, ha, N_A);
    cudaEventRecord(eHA, s1);

    // ---- layer 1 ----
    cudaStreamWaitEvent(s2, eHA, 0);
    agg_mean<<<(N_P + 7) / 8, 256, 0, s2>>>(ha, wptr, widx, aggw, N_P);
    cudaEventRecord(eW1, s2);
    cudaStreamWaitEvent(s0, eCc, 0);
    agg_mean<<<(N_P + 7) / 8, 256, 0, s0>>>(hp, cptr, cidx, aggc, N_P);
    cudaStreamWaitEvent(s0, eW1, 0);
    pgemm<3, 384, 1><<<(N_P + 127) / 128, 256, SMEM_SZ, s0>>>(
        aggc, aggw, hp, wLPh, wLPl,
        bp, nullptr, nullptr, nullptr, zp, N_P);
    cudaEventRecord(eP1, s0);
    cudaStreamWaitEvent(s1, eCr, 0);
    cudaStreamWaitEvent(s1, eHP, 0);
    agg_mean<<<(N_A + 7) / 8, 256, 0, s1>>>(hp, rptr, ridx, aggr, N_A);
    pgemm<2, 256, 1><<<(N_A + 127) / 128, 256, SMEM_SZ, s1>>>(
        aggr, ha, nullptr, wLAh, wLAl,
        bl + 2 * H, nullptr, nullptr, nullptr, za, N_A);
    cudaEventRecord(eZA, s1);

    // ---- layer 2 ----
    cudaStreamWaitEvent(s2, eZA, 0);
    cudaStreamWaitEvent(s2, eP1, 0);
    agg_mean<<<(N_P + 7) / 8, 256, 0, s2>>>(za, wptr, widx, aggw, N_P);
    cudaEventRecord(eW2, s2);
    agg_mean<<<(N_P + 7) / 8, 256, 0, s0>>>(zp, cptr, cidx, aggc, N_P);
    cudaStreamWaitEvent(s0, eW2, 0);
    pgemm<3, 384, 2><<<(N_P + 127) / 128, 256, SMEM_SZ, s0>>>(
        aggc, aggw, zp, wLPh + (size_t)128 * 384, wLPl + (size_t)128 * 384,
        bp + H, nullptr, nullptr, hp, out, N_P);
    cudaStreamWaitEvent(s1, eP1, 0);
    agg_mean<<<(N_A + 7) / 8, 256, 0, s1>>>(zp, rptr, ridx, aggr, N_A);
    pgemm<2, 256, 2><<<(N_A + 127) / 128, 256, SMEM_SZ, s1>>>(
        aggr, za, nullptr, wLAh + (size_t)128 * 256, wLAl + (size_t)128 * 256,
        bl + 5 * H, nullptr, nullptr, ha, out + (size_t)N_P * H, N_A);
    cudaEventRecord(eA2, s1);

    // ---- join ----
    cudaStreamWaitEvent(s0, eA2, 0);

    (void)in_sizes; (void)n_in; (void)out_size;
}

// round 16
// speedup vs baseline: 1.0461x; 1.0461x over previous
#include <cuda_runtime.h>
#include <cuda_bf16.h>
#include <cstdint>

#define N_P 100000
#define N_A 50000
#define E_C 1600000
#define E_W 800000
#define IND 768
#define H   128
#define HH  (128*128)

// ---------------- scratch (device globals; no allocation) ----------------
__device__ float g_hp[(size_t)N_P * H];
__device__ float g_ha[(size_t)N_A * H];
__device__ float g_zp[(size_t)N_P * H];
__device__ float g_za[(size_t)N_A * H];
__device__ float g_aggc[(size_t)N_P * H];
__device__ float g_aggw[(size_t)N_P * H];
__device__ float g_aggr[(size_t)N_A * H];
__device__ float g_bp[2 * H];
__device__ __align__(16) __nv_bfloat16 g_wPh[128 * IND], g_wPl[128 * IND];
__device__ __align__(16) __nv_bfloat16 g_wAh[128 * IND], g_wAl[128 * IND];
__device__ __align__(16) __nv_bfloat16 g_wLPh[2][128 * 384], g_wLPl[2][128 * 384];
__device__ __align__(16) __nv_bfloat16 g_wLAh[2][128 * 256], g_wLAl[2][128 * 256];
__device__ int g_cptr[N_P + 1], g_cidx[E_C];
__device__ int g_wptr[N_P + 1], g_widx[E_W];
__device__ int g_rptr[N_A + 1], g_ridx[E_W];
__device__ int g_tmpA[N_P + 1];
__device__ int g_bsA[136];

// ---------------- helpers ----------------
__device__ __forceinline__ uint32_t s2u(const void* p) {
    uint32_t a;
    asm("{ .reg .u64 t; cvta.to.shared.u64 t, %1; cvt.u32.u64 %0, t; }" : "=r"(a) : "l"(p));
    return a;
}

__device__ __forceinline__ void ldsm4(uint32_t addr, uint32_t* r) {
    asm volatile("ldmatrix.sync.aligned.m8n8.x4.shared.b16 {%0,%1,%2,%3}, [%4];"
                 : "=r"(r[0]), "=r"(r[1]), "=r"(r[2]), "=r"(r[3]) : "r"(addr));
}

__device__ __forceinline__ void mma16816(float* c, const uint32_t* a, uint32_t b0, uint32_t b1) {
    asm volatile("mma.sync.aligned.m16n8k16.row.col.f32.bf16.bf16.f32 "
                 "{%0,%1,%2,%3}, {%4,%5,%6,%7}, {%8,%9}, {%0,%1,%2,%3};"
                 : "+f"(c[0]), "+f"(c[1]), "+f"(c[2]), "+f"(c[3])
                 : "r"(a[0]), "r"(a[1]), "r"(a[2]), "r"(a[3]), "r"(b0), "r"(b1));
}

__device__ __forceinline__ void cpa16(uint32_t dst, const void* src, int sz) {
    asm volatile("cp.async.cg.shared.global [%0], [%1], 16, %2;"
                 :: "r"(dst), "l"(src), "r"(sz));
}
#define CP_COMMIT() asm volatile("cp.async.commit_group;" ::: "memory")

__device__ __forceinline__ uint32_t prmt7632(uint32_t a, uint32_t b) {
    uint32_t d; asm("prmt.b32 %0, %1, %2, 0x7632;" : "=r"(d) : "r"(a), "r"(b)); return d;
}
__device__ __forceinline__ float lopart(uint32_t xb) {
    float x = __uint_as_float(xb);
    return x - __uint_as_float(xb & 0xffff0000u);
}
__device__ __forceinline__ uint32_t bf16x2pack(float hi, float lo) {
    uint32_t d; asm("cvt.rn.bf16x2.f32 %0, %1, %2;" : "=r"(d) : "f"(hi), "f"(lo)); return d;
}

__device__ __forceinline__ void split_bf16(float v, __nv_bfloat16& h, __nv_bfloat16& l) {
    h = __float2bfloat16(v);
    l = __float2bfloat16(v - __bfloat162float(h));
}

__host__ __device__ __forceinline__ int permk(int k) {
    return (k & ~15) | (k & 8) | ((k & 3) << 1) | ((k >> 2) & 1);
}

// ---------------- weight prep ----------------
__global__ void prep_projw(const float* __restrict__ W, __nv_bfloat16* __restrict__ hi,
                           __nv_bfloat16* __restrict__ lo) {
    int i = blockIdx.x * 256 + threadIdx.x;
    if (i >= IND * 128) return;
    int k = i >> 7, n = i & 127;
    __nv_bfloat16 h, l;
    split_bf16(W[i], h, l);
    int kk = permk(k);
    hi[n * IND + kk] = h;
    lo[n * IND + kk] = l;
}

__global__ void prep_layerw(const float* __restrict__ Wl, const float* __restrict__ bl,
                            const float* __restrict__ Wr) {
    int l = blockIdx.y;
    int i = blockIdx.x * 256 + threadIdx.x;
    if (i >= HH) return;
    int k = i >> 7, n = i & 127;
    int kk = permk(k);
    __nv_bfloat16 h, lo;
    split_bf16(0.5f * Wl[(l * 3 + 0) * HH + i], h, lo);
    g_wLPh[l][n * 384 + kk] = h;       g_wLPl[l][n * 384 + kk] = lo;
    split_bf16(0.5f * Wl[(l * 3 + 1) * HH + i], h, lo);
    g_wLPh[l][n * 384 + 128 + kk] = h; g_wLPl[l][n * 384 + 128 + kk] = lo;
    split_bf16(0.5f * (Wr[(l * 3 + 0) * HH + i] + Wr[(l * 3 + 1) * HH + i]), h, lo);
    g_wLPh[l][n * 384 + 256 + kk] = h; g_wLPl[l][n * 384 + 256 + kk] = lo;
    split_bf16(Wl[(l * 3 + 2) * HH + i], h, lo);
    g_wLAh[l][n * 256 + kk] = h;       g_wLAl[l][n * 256 + kk] = lo;
    split_bf16(Wr[(l * 3 + 2) * HH + i], h, lo);
    g_wLAh[l][n * 256 + 128 + kk] = h; g_wLAl[l][n * 256 + 128 + kk] = lo;
    if (blockIdx.x == 0 && i < H)
        g_bp[l * H + i] = 0.5f * (bl[(l * 3 + 0) * H + i] + bl[(l * 3 + 1) * H + i]);
}

// ---------------- CSR build (hierarchical scan) ----------------
__global__ void zero_int(int* __restrict__ p, int n) {
    int i = blockIdx.x * blockDim.x + threadIdx.x;
    if (i < n) p[i] = 0;
}
__global__ void count_k(const int* __restrict__ dst, int* __restrict__ cnt, int n) {
    int i = blockIdx.x * blockDim.x + threadIdx.x;
    if (i < n) atomicAdd(&cnt[dst[i]], 1);
}
__global__ void scan_blk(const int* __restrict__ cnt, int* __restrict__ ptr,
                         int* __restrict__ bsum, int n) {
    __shared__ int ss[1024];
    int tid = threadIdx.x;
    int i = blockIdx.x * 1024 + tid;
    int v = (i < n) ? cnt[i] : 0;
    ss[tid] = v;
    __syncthreads();
    #pragma unroll
    for (int off = 1; off < 1024; off <<= 1) {
        int t = (tid >= off) ? ss[tid - off] : 0;
        __syncthreads();
        ss[tid] += t;
        __syncthreads();
    }
    if (i < n) ptr[i] = ss[tid] - v;
    if (tid == 1023) bsum[blockIdx.x] = ss[1023];
}
__global__ void scan_top(int* __restrict__ bsum, int nb) {
    __shared__ int ss[128];
    int tid = threadIdx.x;
    int v = (tid < nb) ? bsum[tid] : 0;
    ss[tid] = v;
    __syncthreads();
    #pragma unroll
    for (int off = 1; off < 128; off <<= 1) {
        int t = (tid >= off) ? ss[tid - off] : 0;
        __syncthreads();
        ss[tid] += t;
        __syncthreads();
    }
    if (tid < nb) bsum[tid] = ss[tid] - v;
    if (tid == 127) bsum[nb] = ss[127];
}
__global__ void add_off(int* __restrict__ ptr, const int* __restrict__ bsum, int n, int nb) {
    int i = blockIdx.x * blockDim.x + threadIdx.x;
    if (i < n) ptr[i] += bsum[i >> 10];
    else if (i == n) ptr[n] = bsum[nb];
}
__global__ void fill_k(const int* __restrict__ src, const int* __restrict__ dst,
                       const int* __restrict__ ptr, int* __restrict__ tmp,
                       int* __restrict__ cidx, int n) {
    int i = blockIdx.x * blockDim.x + threadIdx.x;
    if (i < n) {
        int d = dst[i];
        int p = atomicAdd(&tmp[d], 1);
        cidx[ptr[d] + p] = src[i];
    }
}

// ---------------- mean aggregation: one warp per destination node ----------------
__global__ void agg_mean(const float* __restrict__ feat, const int* __restrict__ ptr,
                         const int* __restrict__ idx, float* __restrict__ out, int n) {
    int w = (blockIdx.x * blockDim.x + threadIdx.x) >> 5;
    int lane = threadIdx.x & 31;
    if (w >= n) return;
    int beg = ptr[w], end = ptr[w + 1];
    float ax = 0.f, ay = 0.f, az = 0.f, aw = 0.f;
    int e = beg;
    for (; e + 4 <= end; e += 4) {
        int s0 = idx[e], s1 = idx[e + 1], s2 = idx[e + 2], s3 = idx[e + 3];
        float4 v0 = ((const float4*)(feat + (size_t)s0 * H))[lane];
        float4 v1 = ((const float4*)(feat + (size_t)s1 * H))[lane];
        float4 v2 = ((const float4*)(feat + (size_t)s2 * H))[lane];
        float4 v3 = ((const float4*)(feat + (size_t)s3 * H))[lane];
        ax += (v0.x + v1.x) + (v2.x + v3.x);
        ay += (v0.y + v1.y) + (v2.y + v3.y);
        az += (v0.z + v1.z) + (v2.z + v3.z);
        aw += (v0.w + v1.w) + (v2.w + v3.w);
    }
    for (; e < end; e++) {
        int s0 = idx[e];
        float4 v0 = ((const float4*)(feat + (size_t)s0 * H))[lane];
        ax += v0.x; ay += v0.y; az += v0.z; aw += v0.w;
    }
    int c = end - beg;
    float inv = 1.0f / (float)(c > 1 ? c : 1);
    float4 r;
    r.x = ax * inv; r.y = ay * inv; r.z = az * inv; r.w = aw * inv;
    ((float4*)(out + (size_t)w * H))[lane] = r;
}

// ---------------- async pipelined warp-MMA GEMM (register-neutral phase-major MMAs) ----------------
#define SMEM_SZ 65536
template <int NMAT, int KC, int EPI>
__global__ __launch_bounds__(256, 2) void pgemm(
    const float* __restrict__ A0, const float* __restrict__ A1, const float* __restrict__ A2,
    const __nv_bfloat16* __restrict__ Bhi, const __nv_bfloat16* __restrict__ Blo,
    const float* __restrict__ bias, const float* __restrict__ lng, const float* __restrict__ lnb,
    const float* __restrict__ res, float* __restrict__ out, int M) {
    extern __shared__ char sm[];
    uint32_t sbase = s2u(sm);
    int t = threadIdx.x, lane = t & 31, wid = t >> 5;
    int wm = wid & 3, wn = wid >> 2;
    int row0 = blockIdx.x * 128;
    const int SEG = KC / NMAT;
    const int NI = KC / 32;
    const float* Aall[3] = {A0, A1, A2};

    int q = lane >> 3, e = lane & 7;

    float acc[2][8][4];
    #pragma unroll
    for (int a = 0; a < 2; a++)
        #pragma unroll
        for (int b = 0; b < 8; b++)
            #pragma unroll
            for (int c = 0; c < 4; c++) acc[a][b][c] = 0.f;

    auto stage = [&](int i) {
        int b = i & 1;
        int k0 = i * 32;
        int mseg = k0 / SEG, kl = k0 - mseg * SEG;
        const float* A = Aall[mseg];
        #pragma unroll
        for (int it = 0; it < 4; it++) {
            int uid = t + 256 * it;
            int r = uid >> 3, u = uid & 7;
            int gr = row0 + r;
            int ok = (gr < M);
            const float* src = A + (size_t)(ok ? gr : 0) * SEG + kl + 4 * u;
            uint32_t dst = sbase + b * 16384 + (uint32_t)(r * 128 + ((u ^ (r & 7)) << 4));
            cpa16(dst, src, ok ? 16 : 0);
        }
        #pragma unroll
        for (int it = 0; it < 2; it++) {
            int uid = t + 256 * it;
            int n = uid >> 2, v = uid & 3;
            size_t go = (size_t)n * KC + k0 + 8 * v;
            uint32_t off = (uint32_t)(n * 64 + ((v ^ ((n >> 1) & 3)) << 4));
            cpa16(sbase + 32768 + b * 8192 + off, Bhi + go, 16);
            cpa16(sbase + 49152 + b * 8192 + off, Blo + go, 16);
        }
        CP_COMMIT();
    };

    stage(0);
    for (int i = 0; i < NI; i++) {
        if (i + 1 < NI) {
            stage(i + 1);
            asm volatile("cp.async.wait_group 1;" ::: "memory");
        } else {
            asm volatile("cp.async.wait_group 0;" ::: "memory");
        }
        __syncthreads();
        int b = i & 1;
        uint32_t aB = sbase + b * 16384;
        uint32_t bhB = sbase + 32768 + b * 8192;
        uint32_t blB = sbase + 49152 + b * 8192;
        #pragma unroll
        for (int ks = 0; ks < 2; ks++) {
            uint32_t AH[2][4], AL[2][4];
            #pragma unroll
            for (int mt = 0; mt < 2; mt++) {
                int arow = wm * 32 + mt * 16 + (q & 1) * 8 + e;
                uint32_t ro = (uint32_t)(arow * 128);
                int u1 = 4 * ks + (q >> 1);
                int u2 = u1 + 2;
                uint32_t x[8];
                ldsm4(aB + ro + (uint32_t)((u1 ^ (arow & 7)) << 4), x);
                ldsm4(aB + ro + (uint32_t)((u2 ^ (arow & 7)) << 4), x + 4);
                AH[mt][0] = prmt7632(x[0], x[2]);
                AH[mt][1] = prmt7632(x[1], x[3]);
                AH[mt][2] = prmt7632(x[4], x[6]);
                AH[mt][3] = prmt7632(x[5], x[7]);
                AL[mt][0] = bf16x2pack(lopart(x[2]), lopart(x[0]));
                AL[mt][1] = bf16x2pack(lopart(x[3]), lopart(x[1]));
                AL[mt][2] = bf16x2pack(lopart(x[6]), lopart(x[4]));
                AL[mt][3] = bf16x2pack(lopart(x[7]), lopart(x[5]));
            }
            #pragma unroll
            for (int nt2 = 0; nt2 < 4; nt2++) {
                int brow = wn * 64 + nt2 * 16 + (q & 1) * 8 + e;
                int v = 2 * ks + (q >> 1);
                uint32_t bo = (uint32_t)(brow * 64 + ((v ^ ((brow >> 1) & 3)) << 4));
                uint32_t bh[4], bl[4];
                ldsm4(bhB + bo, bh);
                ldsm4(blB + bo, bl);
                // phase-major: 3 phases of 4 independent MMAs (register-neutral)
                #pragma unroll
                for (int mt = 0; mt < 2; mt++)
                    #pragma unroll
                    for (int s = 0; s < 2; s++)
                        mma16816(acc[mt][2 * nt2 + s], AH[mt], bh[s], bh[2 + s]);
                #pragma unroll
                for (int mt = 0; mt < 2; mt++)
                    #pragma unroll
                    for (int s = 0; s < 2; s++)
                        mma16816(acc[mt][2 * nt2 + s], AH[mt], bl[s], bl[2 + s]);
                #pragma unroll
                for (int mt = 0; mt < 2; mt++)
                    #pragma unroll
                    for (int s = 0; s < 2; s++)
                        mma16816(acc[mt][2 * nt2 + s], AL[mt], bh[s], bh[2 + s]);
            }
        }
        __syncthreads();
    }

    // ---- epilogue ----
    int la = lane >> 2, lc = 2 * (lane & 3);
    float2 b2[8];
    #pragma unroll
    for (int nt = 0; nt < 8; nt++)
        b2[nt] = *(const float2*)(bias + wn * 64 + nt * 8 + lc);
    #pragma unroll
    for (int mt = 0; mt < 2; mt++)
        #pragma unroll
        for (int nt = 0; nt < 8; nt++) {
            acc[mt][nt][0] += b2[nt].x; acc[mt][nt][1] += b2[nt].y;
            acc[mt][nt][2] += b2[nt].x; acc[mt][nt][3] += b2[nt].y;
        }

    if (EPI == 0) {
        float* red = (float*)sm;
        float s1[2][2], s2[2][2];
        #pragma unroll
        for (int mt = 0; mt < 2; mt++)
            #pragma unroll
            for (int h = 0; h < 2; h++) {
                float a1 = 0.f, a2 = 0.f;
                #pragma unroll
                for (int nt = 0; nt < 8; nt++) {
                    float vx = acc[mt][nt][2 * h], vy = acc[mt][nt][2 * h + 1];
                    a1 += vx + vy;
                    a2 += vx * vx + vy * vy;
                }
                a1 += __shfl_xor_sync(0xffffffffu, a1, 1);
                a1 += __shfl_xor_sync(0xffffffffu, a1, 2);
                a2 += __shfl_xor_sync(0xffffffffu, a2, 1);
                a2 += __shfl_xor_sync(0xffffffffu, a2, 2);
                s1[mt][h] = a1; s2[mt][h] = a2;
            }
        if ((lane & 3) == 0) {
            #pragma unroll
            for (int mt = 0; mt < 2; mt++)
                #pragma unroll
                for (int h = 0; h < 2; h++) {
                    int rl = wm * 32 + mt * 16 + la + h * 8;
                    red[(wn * 128 + rl) * 2 + 0] = s1[mt][h];
                    red[(wn * 128 + rl) * 2 + 1] = s2[mt][h];
                }
        }
        __syncthreads();
        float2 lg2[8], lb2[8];
        #pragma unroll
        for (int nt = 0; nt < 8; nt++) {
            lg2[nt] = *(const float2*)(lng + wn * 64 + nt * 8 + lc);
            lb2[nt] = *(const float2*)(lnb + wn * 64 + nt * 8 + lc);
        }
        #pragma unroll
        for (int mt = 0; mt < 2; mt++)
            #pragma unroll
            for (int h = 0; h < 2; h++) {
                int rl = wm * 32 + mt * 16 + la + h * 8;
                float o1 = red[((1 - wn) * 128 + rl) * 2 + 0];
                float o2 = red[((1 - wn) * 128 + rl) * 2 + 1];
                float mu = (s1[mt][h] + o1) * (1.0f / 128.0f);
                float ex2 = (s2[mt][h] + o2) * (1.0f / 128.0f);
                float rstd = rsqrtf(fmaxf(ex2 - mu * mu, 0.f) + 1e-5f);
                #pragma unroll
                for (int nt = 0; nt < 8; nt++) {
                    float vx = acc[mt][nt][2 * h], vy = acc[mt][nt][2 * h + 1];
                    vx = fmaxf((vx - mu) * rstd * lg2[nt].x + lb2[nt].x, 0.f);
                    vy = fmaxf((vy - mu) * rstd * lg2[nt].y + lb2[nt].y, 0.f);
                    acc[mt][nt][2 * h] = vx; acc[mt][nt][2 * h + 1] = vy;
                }
            }
    } else {
        #pragma unroll
        for (int mt = 0; mt < 2; mt++)
            #pragma unroll
            for (int nt = 0; nt < 8; nt++)
                #pragma unroll
                for (int c = 0; c < 4; c++)
                    acc[mt][nt][c] = fmaxf(acc[mt][nt][c], 0.f);
    }

    #pragma unroll
    for (int mt = 0; mt < 2; mt++)
        #pragma unroll
        for (int h = 0; h < 2; h++) {
            int row = row0 + wm * 32 + mt * 16 + la + h * 8;
            if (row < M) {
                #pragma unroll
                for (int nt = 0; nt < 8; nt++) {
                    int col = wn * 64 + nt * 8 + lc;
                    float vx = acc[mt][nt][2 * h], vy = acc[mt][nt][2 * h + 1];
                    if (EPI == 2) {
                        float2 rv = *(const float2*)(res + (size_t)row * H + col);
                        vx += rv.x; vy += rv.y;
                    }
                    float2 o; o.x = vx; o.y = vy;
                    *(float2*)(out + (size_t)row * H + col) = o;
                }
            }
        }
}

// ---------------- launch: forked-stream graph (2 extra streams, proven footprint) ----------------
extern "C" void kernel_launch(void* const* d_in, const int* in_sizes, int n_in,
                              void* d_out, int out_size) {
    const float* x_paper   = (const float*)d_in[0];
    const float* x_author  = (const float*)d_in[1];
    const float* pw_paper  = (const float*)d_in[2];
    const float* pb_paper  = (const float*)d_in[3];
    const float* lng_paper = (const float*)d_in[4];
    const float* lnb_paper = (const float*)d_in[5];
    const float* pw_author  = (const float*)d_in[6];
    const float* pb_author  = (const float*)d_in[7];
    const float* lng_author = (const float*)d_in[8];
    const float* lnb_author = (const float*)d_in[9];
    const float* Wl = (const float*)d_in[10];
    const float* bl = (const float*)d_in[11];
    const float* Wr = (const float*)d_in[12];
    const int* cs = (const int*)d_in[13];
    const int* cd = (const int*)d_in[14];
    const int* ws = (const int*)d_in[15];
    const int* wd = (const int*)d_in[16];
    const int* rs = (const int*)d_in[17];
    const int* rd = (const int*)d_in[18];
    float* out = (float*)d_out;

    float *hp, *ha, *zp, *za, *aggc, *aggw, *aggr, *bp;
    __nv_bfloat16 *wPh, *wPl, *wAh, *wAl, *wLPh, *wLPl, *wLAh, *wLAl;
    int *cptr, *cidx, *wptr, *widx, *rptr, *ridx, *tmpA, *bsA;
    cudaGetSymbolAddress((void**)&hp, g_hp);
    cudaGetSymbolAddress((void**)&ha, g_ha);
    cudaGetSymbolAddress((void**)&zp, g_zp);
    cudaGetSymbolAddress((void**)&za, g_za);
    cudaGetSymbolAddress((void**)&aggc, g_aggc);
    cudaGetSymbolAddress((void**)&aggw, g_aggw);
    cudaGetSymbolAddress((void**)&aggr, g_aggr);
    cudaGetSymbolAddress((void**)&bp, g_bp);
    cudaGetSymbolAddress((void**)&wPh, g_wPh);
    cudaGetSymbolAddress((void**)&wPl, g_wPl);
    cudaGetSymbolAddress((void**)&wAh, g_wAh);
    cudaGetSymbolAddress((void**)&wAl, g_wAl);
    cudaGetSymbolAddress((void**)&wLPh, g_wLPh);
    cudaGetSymbolAddress((void**)&wLPl, g_wLPl);
    cudaGetSymbolAddress((void**)&wLAh, g_wLAh);
    cudaGetSymbolAddress((void**)&wLAl, g_wLAl);
    cudaGetSymbolAddress((void**)&cptr, g_cptr);
    cudaGetSymbolAddress((void**)&cidx, g_cidx);
    cudaGetSymbolAddress((void**)&wptr, g_wptr);
    cudaGetSymbolAddress((void**)&widx, g_widx);
    cudaGetSymbolAddress((void**)&rptr, g_rptr);
    cudaGetSymbolAddress((void**)&ridx, g_ridx);
    cudaGetSymbolAddress((void**)&tmpA, g_tmpA);
    cudaGetSymbolAddress((void**)&bsA, g_bsA);

    cudaFuncSetAttribute(pgemm<1, IND, 0>, cudaFuncAttributeMaxDynamicSharedMemorySize, SMEM_SZ);
    cudaFuncSetAttribute(pgemm<3, 384, 1>, cudaFuncAttributeMaxDynamicSharedMemorySize, SMEM_SZ);
    cudaFuncSetAttribute(pgemm<2, 256, 1>, cudaFuncAttributeMaxDynamicSharedMemorySize, SMEM_SZ);
    cudaFuncSetAttribute(pgemm<3, 384, 2>, cudaFuncAttributeMaxDynamicSharedMemorySize, SMEM_SZ);
    cudaFuncSetAttribute(pgemm<2, 256, 2>, cudaFuncAttributeMaxDynamicSharedMemorySize, SMEM_SZ);

    static cudaStream_t s1 = nullptr, s2 = nullptr;
    static cudaEvent_t eFork = nullptr, eHP = nullptr, eHA = nullptr,
                       eCc = nullptr, eCr = nullptr, eW1 = nullptr, eW2 = nullptr,
                       eP1 = nullptr, eZA = nullptr, eA2 = nullptr;
    if (!s1) {
        cudaStreamCreateWithFlags(&s1, cudaStreamNonBlocking);
        cudaStreamCreateWithFlags(&s2, cudaStreamNonBlocking);
        cudaEventCreateWithFlags(&eFork, cudaEventDisableTiming);
        cudaEventCreateWithFlags(&eHP, cudaEventDisableTiming);
        cudaEventCreateWithFlags(&eHA, cudaEventDisableTiming);
        cudaEventCreateWithFlags(&eCc, cudaEventDisableTiming);
        cudaEventCreateWithFlags(&eCr, cudaEventDisableTiming);
        cudaEventCreateWithFlags(&eW1, cudaEventDisableTiming);
        cudaEventCreateWithFlags(&eW2, cudaEventDisableTiming);
        cudaEventCreateWithFlags(&eP1, cudaEventDisableTiming);
        cudaEventCreateWithFlags(&eZA, cudaEventDisableTiming);
        cudaEventCreateWithFlags(&eA2, cudaEventDisableTiming);
    }
    cudaStream_t s0 = 0;

    // ---- fork ----
    cudaEventRecord(eFork, s0);
    cudaStreamWaitEvent(s1, eFork, 0);
    cudaStreamWaitEvent(s2, eFork, 0);

    auto build = [&](cudaStream_t st, const int* s, const int* d, int nn, int ne,
                     int* ptr, int* ci) {
        int nb = (nn + 1023) >> 10;
        zero_int<<<(nn + 255) / 256, 256, 0, st>>>(tmpA, nn);
        count_k<<<(ne + 255) / 256, 256, 0, st>>>(d, tmpA, ne);
        scan_blk<<<nb, 1024, 0, st>>>(tmpA, ptr, bsA, nn);
        scan_top<<<1, 128, 0, st>>>(bsA, nb);
        add_off<<<(nn + 256) / 256, 256, 0, st>>>(ptr, bsA, nn, nb);
        zero_int<<<(nn + 255) / 256, 256, 0, st>>>(tmpA, nn);
        fill_k<<<(ne + 255) / 256, 256, 0, st>>>(s, d, ptr, tmpA, ci, ne);
    };

    // ---- s2: layer weights + all CSR builds (hidden under projections) ----
    {
        dim3 g((HH + 255) / 256, 2);
        prep_layerw<<<g, 256, 0, s2>>>(Wl, bl, Wr);
    }
    build(s2, cs, cd, N_P, E_C, cptr, cidx);
    cudaEventRecord(eCc, s2);
    build(s2, rs, rd, N_A, E_W, rptr, ridx);
    cudaEventRecord(eCr, s2);
    build(s2, ws, wd, N_P, E_W, wptr, widx);

    // ---- s0: paper projection ----
    prep_projw<<<(IND * 128 + 255) / 256, 256, 0, s0>>>(pw_paper, wPh, wPl);
    pgemm<1, IND, 0><<<(N_P + 127) / 128, 256, SMEM_SZ, s0>>>(
        x_paper, nullptr, nullptr, wPh, wPl,
        pb_paper, lng_paper, lnb_paper, nullptr, hp, N_P);
    cudaEventRecord(eHP, s0);

    // ---- s1: author projection ----
    prep_projw<<<(IND * 128 + 255) / 256, 256, 0, s1>>>(pw_author, wAh, wAl);
    pgemm<1, IND, 0><<<(N_A + 127) / 128, 256, SMEM_SZ, s1>>>(
        x_author, nullptr, nullptr, wAh, wAl,
        pb_author, lng_author, lnb_author, nullptr, ha, N_A);
    cudaEventRecord(eHA, s1);

    // ---- layer 1 ----
    cudaStreamWaitEvent(s2, eHA, 0);
    agg_mean<<<(N_P + 7) / 8, 256, 0, s2>>>(ha, wptr, widx, aggw, N_P);
    cudaEventRecord(eW1, s2);
    cudaStreamWaitEvent(s0, eCc, 0);
    agg_mean<<<(N_P + 7) / 8, 256, 0, s0>>>(hp, cptr, cidx, aggc, N_P);
    cudaStreamWaitEvent(s0, eW1, 0);
    pgemm<3, 384, 1><<<(N_P + 127) / 128, 256, SMEM_SZ, s0>>>(
        aggc, aggw, hp, wLPh, wLPl,
        bp, nullptr, nullptr, nullptr, zp, N_P);
    cudaEventRecord(eP1, s0);
    cudaStreamWaitEvent(s1, eCr, 0);
    cudaStreamWaitEvent(s1, eHP, 0);
    agg_mean<<<(N_A + 7) / 8, 256, 0, s1>>>(hp, rptr, ridx, aggr, N_A);
    pgemm<2, 256, 1><<<(N_A + 127) / 128, 256, SMEM_SZ, s1>>>(
        aggr, ha, nullptr, wLAh, wLAl,
        bl + 2 * H, nullptr, nullptr, nullptr, za, N_A);
    cudaEventRecord(eZA, s1);

    // ---- layer 2 ----
    cudaStreamWaitEvent(s2, eZA, 0);
    cudaStreamWaitEvent(s2, eP1, 0);
    agg_mean<<<(N_P + 7) / 8, 256, 0, s2>>>(za, wptr, widx, aggw, N_P);
    cudaEventRecord(eW2, s2);
    agg_mean<<<(N_P + 7) / 8, 256, 0, s0>>>(zp, cptr, cidx, aggc, N_P);
    cudaStreamWaitEvent(s0, eW2, 0);
    pgemm<3, 384, 2><<<(N_P + 127) / 128, 256, SMEM_SZ, s0>>>(
        aggc, aggw, zp, wLPh + (size_t)128 * 384, wLPl + (size_t)128 * 384,
        bp + H, nullptr, nullptr, hp, out, N_P);
    cudaStreamWaitEvent(s1, eP1, 0);
    agg_mean<<<(N_A + 7) / 8, 256, 0, s1>>>(zp, rptr, ridx, aggr, N_A);
    pgemm<2, 256, 2><<<(N_A + 127) / 128, 256, SMEM_SZ, s1>>>(
        aggr, za, nullptr, wLAh + (size_t)128 * 256, wLAl + (size_t)128 * 256,
        bl + 5 * H, nullptr, nullptr, ha, out + (size_t)N_P * H, N_A);
    cudaEventRecord(eA2, s1);

    // ---- join ----
    cudaStreamWaitEvent(s0, eA2, 0);

    (void)in_sizes; (void)n_in; (void)out_size;
}